// round 2
// baseline (speedup 1.0000x reference)
#include <cuda_runtime.h>
#include <cuda_bf16.h>
#include <cstdint>

// Problem constants
#define BB 64
#define TT 512
#define EE 2048
#define KK 32

// Scratch (device globals: no allocation allowed)
__device__ float g_logits[BB * TT * KK];   // 4 MB
__device__ float g_partial[BB];

// ---------------------------------------------------------------------------
// packed f32x2 helpers (sm_103a)
// ---------------------------------------------------------------------------
static __device__ __forceinline__ unsigned long long pack2(float lo, float hi) {
    unsigned long long d;
    asm("mov.b64 %0, {%1, %2};" : "=l"(d) : "f"(lo), "f"(hi));
    return d;
}
static __device__ __forceinline__ void ffma2(unsigned long long& acc,
                                             unsigned long long a,
                                             unsigned long long b) {
    asm("fma.rn.f32x2 %0, %1, %2, %0;" : "+l"(acc) : "l"(a), "l"(b));
}

// ---------------------------------------------------------------------------
// GEMM: g_logits[m, j] = sum_e X[m, e] * W[e, j] + b[j]
//   M = B*T = 32768, E = 2048, K(out) = 32
// Block: 256 threads, 256 rows per block, grid = 128.
// Thread: 4 rows x 8 cols (4 f32x2 pairs). E tiled by 32 through shared.
// ---------------------------------------------------------------------------
#define TE 32
#define BLK_ROWS 256

__global__ void __launch_bounds__(256) gemm_kernel(const float* __restrict__ X,
                                                   const float* __restrict__ W,
                                                   const float* __restrict__ bias) {
    __shared__ float Xs[TE][257];   // [e][row], stride 257 -> conflict-free
    __shared__ float Ws[TE][KK];

    const int tid = threadIdx.x;
    const int jg  = tid & 3;     // j base = jg*8
    const int rg  = tid >> 2;    // rows rg*4 .. rg*4+3
    const int row0 = blockIdx.x * BLK_ROWS;
    const int jbase = jg * 8;

    // init accumulators with bias (added once)
    unsigned long long acc[4][4];
    {
        unsigned long long binit[4];
#pragma unroll
        for (int u = 0; u < 4; u++)
            binit[u] = pack2(bias[jbase + 2 * u], bias[jbase + 2 * u + 1]);
#pragma unroll
        for (int r = 0; r < 4; r++)
#pragma unroll
            for (int u = 0; u < 4; u++) acc[r][u] = binit[u];
    }

    const float* Xg = X + (size_t)row0 * EE;

    for (int e0 = 0; e0 < EE; e0 += TE) {
        __syncthreads();
        // load X tile: 256 rows x 32 e = 2048 float4, 8 per thread (coalesced)
#pragma unroll
        for (int l = 0; l < 8; l++) {
            int fi = tid + l * 256;
            int r  = fi >> 3;
            int c  = (fi & 7) * 4;
            float4 v = *(const float4*)(Xg + (size_t)r * EE + e0 + c);
            Xs[c + 0][r] = v.x;
            Xs[c + 1][r] = v.y;
            Xs[c + 2][r] = v.z;
            Xs[c + 3][r] = v.w;
        }
        // load W tile: 32 e x 32 j = 1024 floats contiguous, 1 float4/thread
        {
            const float* Wg = W + e0 * KK;
            float4 v = *(const float4*)(Wg + tid * 4);
            int e = tid >> 3;
            int j = (tid & 7) * 4;
            *(float4*)&Ws[e][j] = v;
        }
        __syncthreads();

#pragma unroll 8
        for (int e = 0; e < TE; e++) {
            unsigned long long w[4];
#pragma unroll
            for (int u = 0; u < 4; u++)
                w[u] = *(const unsigned long long*)&Ws[e][jbase + 2 * u];
#pragma unroll
            for (int r = 0; r < 4; r++) {
                float x = Xs[e][rg * 4 + r];
                unsigned long long xx = pack2(x, x);
#pragma unroll
                for (int u = 0; u < 4; u++) ffma2(acc[r][u], xx, w[u]);
            }
        }
    }

    // store (bit-identical pair store)
    float* out = g_logits + (size_t)row0 * KK;
#pragma unroll
    for (int r = 0; r < 4; r++) {
        int row = rg * 4 + r;
#pragma unroll
        for (int u = 0; u < 4; u++)
            *(unsigned long long*)&out[row * KK + jbase + 2 * u] = acc[r][u];
    }
}

// ---------------------------------------------------------------------------
// CRF kernel: one warp per batch. lane = tag j.
// Probability-space forward recurrence + joint path score.
// mask is read as 4-byte words, tested != 0 (works for int32 0/1, uint32,
// and float32 0.0/1.0 encodings).
// ---------------------------------------------------------------------------
__global__ void __launch_bounds__(32) crf_kernel(const int* __restrict__ y,
                                                 const unsigned int* __restrict__ mask,
                                                 const float* __restrict__ trans,
                                                 const float* __restrict__ startT,
                                                 const float* __restrict__ endT) {
    const int b = blockIdx.x;
    const int j = threadIdx.x;
    const float* L = g_logits + (size_t)b * TT * KK;
    const unsigned int* mk = mask + b * TT;
    const int* yb = y + b * TT;

    // ---- sequence length (mask is a prefix) ----
    int cnt = 0;
    for (int t = j; t < TT; t += 32) cnt += (mk[t] != 0u);
#pragma unroll
    for (int o = 16; o; o >>= 1) cnt += __shfl_xor_sync(0xffffffffu, cnt, o);
    const int len = cnt;   // >= T/2 >= 1

    // ---- joint (numerator) path score ----
    float num = 0.f;
    for (int t = j; t < TT; t += 32) {
        if (mk[t] != 0u) {
            int yt = yb[t];
            num += L[t * KK + yt];
            if (t > 0) num += trans[yb[t - 1] * KK + yt];
        }
    }
#pragma unroll
    for (int o = 16; o; o >>= 1) num += __shfl_xor_sync(0xffffffffu, num, o);
    if (j == 0) num += startT[yb[0]] + endT[yb[len - 1]];

    // ---- forward algorithm (denominator), probability space ----
    float ET[KK];  // exp(trans[i][j]) column for this lane's j
#pragma unroll
    for (int i = 0; i < KK; i++) ET[i] = __expf(trans[i * KK + j]);
    const float ej = endT[j];

    __shared__ float psh[2][KK];

    float a0 = startT[j] + L[j];
    float m = a0;
#pragma unroll
    for (int o = 16; o; o >>= 1) m = fmaxf(m, __shfl_xor_sync(0xffffffffu, m, o));
    float p = __expf(a0 - m);
    float s = m;
    psh[0][j] = p;
    __syncwarp();

    int buf = 0;
    float xnext = (len > 1) ? L[KK + j] : 0.f;
    for (int t = 1; t < len; t++) {
        float x = xnext;
        if (t + 1 < len) xnext = L[(t + 1) * KK + j];   // prefetch next step
        const float* pb = psh[buf];
        float r0 = 0.f, r1 = 0.f, r2 = 0.f, r3 = 0.f;
#pragma unroll
        for (int i = 0; i < KK; i += 4) {
            r0 = fmaf(pb[i + 0], ET[i + 0], r0);
            r1 = fmaf(pb[i + 1], ET[i + 1], r1);
            r2 = fmaf(pb[i + 2], ET[i + 2], r2);
            r3 = fmaf(pb[i + 3], ET[i + 3], r3);
        }
        float r = (r0 + r1) + (r2 + r3);
        p = r * __expf(x);
        if ((t & 7) == 0) {  // renormalize every 8 steps (overflow-safe window)
            float mx = p;
#pragma unroll
            for (int o = 16; o; o >>= 1)
                mx = fmaxf(mx, __shfl_xor_sync(0xffffffffu, mx, o));
            s += __logf(mx);
            p *= __frcp_rn(mx);
        }
        buf ^= 1;
        psh[buf][j] = p;
        __syncwarp();
    }

    float q = p * __expf(ej);
#pragma unroll
    for (int o = 16; o; o >>= 1) q += __shfl_xor_sync(0xffffffffu, q, o);
    float den = s + __logf(q);

    if (j == 0) g_partial[b] = num - den;
}

// ---------------------------------------------------------------------------
// Final reduction: loss = -sum_b (num_b - den_b)
// ---------------------------------------------------------------------------
__global__ void __launch_bounds__(32) reduce_kernel(float* __restrict__ out) {
    int j = threadIdx.x;
    float v = g_partial[j] + g_partial[j + 32];
#pragma unroll
    for (int o = 16; o; o >>= 1) v += __shfl_xor_sync(0xffffffffu, v, o);
    if (j == 0) out[0] = -v;
}

// ---------------------------------------------------------------------------
extern "C" void kernel_launch(void* const* d_in, const int* in_sizes, int n_in,
                              void* d_out, int out_size) {
    const float*         X     = (const float*)d_in[0];
    const int*           y     = (const int*)d_in[1];
    const unsigned int*  mask  = (const unsigned int*)d_in[2];
    const float*         W     = (const float*)d_in[3];
    const float*         bias  = (const float*)d_in[4];
    const float*         trans = (const float*)d_in[5];
    const float*         stt   = (const float*)d_in[6];
    const float*         endt  = (const float*)d_in[7];
    float* out = (float*)d_out;

    gemm_kernel<<<(BB * TT) / BLK_ROWS, 256>>>(X, W, bias);
    crf_kernel<<<BB, 32>>>(y, mask, trans, stt, endt);
    reduce_kernel<<<1, 32>>>(out);
}

// round 3
// speedup vs baseline: 1.1878x; 1.1878x over previous
#include <cuda_runtime.h>
#include <cuda_bf16.h>
#include <cstdint>

// Problem constants
#define BB 64
#define TT 512
#define EE 2048
#define KK 32

// Scratch (device globals: no allocation allowed)
__device__ float g_logits[BB * TT * KK];   // 4 MB
__device__ float g_partial[BB];

// ---------------------------------------------------------------------------
// packed f32x2 helpers (sm_103a)
// ---------------------------------------------------------------------------
static __device__ __forceinline__ unsigned long long pack2(float lo, float hi) {
    unsigned long long d;
    asm("mov.b64 %0, {%1, %2};" : "=l"(d) : "f"(lo), "f"(hi));
    return d;
}
static __device__ __forceinline__ void ffma2(unsigned long long& acc,
                                             unsigned long long a,
                                             unsigned long long b) {
    asm("fma.rn.f32x2 %0, %1, %2, %0;" : "+l"(acc) : "l"(a), "l"(b));
}
static __device__ __forceinline__ void unpack2(float& lo, float& hi,
                                               unsigned long long v) {
    asm("mov.b64 {%0, %1}, %2;" : "=f"(lo), "=f"(hi) : "l"(v));
}
static __device__ __forceinline__ void cp_async16(void* dst, const void* src) {
    unsigned sdst = (unsigned)__cvta_generic_to_shared(dst);
    asm volatile("cp.async.cg.shared.global [%0], [%1], 16;\n"
                 :: "r"(sdst), "l"(src));
}
#define CP_COMMIT() asm volatile("cp.async.commit_group;\n" ::: "memory")
#define CP_WAIT1()  asm volatile("cp.async.wait_group 1;\n" ::: "memory")
#define CP_WAIT0()  asm volatile("cp.async.wait_group 0;\n" ::: "memory")

// ---------------------------------------------------------------------------
// GEMM: g_logits[m, j] = sum_e X[m, e] * W[e, j] + b[j]
//   M = 32768, E = 2048, Kout = 32
// 256 blocks x 256 threads, 128 rows/block.
// Thread: rows (rg, rg+64), cols jbase..jbase+7 (4 f32x2 accumulators each).
// Double-buffered tiles via cp.async.
// ---------------------------------------------------------------------------
#define TE 32
#define ROWS_PER_BLK 128
#define XPITCH 36   // 36 floats = 144B: 16B-aligned rows, conflict-free column reads

__global__ void __launch_bounds__(256) gemm_kernel(const float* __restrict__ X,
                                                   const float* __restrict__ W,
                                                   const float* __restrict__ bias) {
    __shared__ __align__(16) float Xs[2][ROWS_PER_BLK][XPITCH];
    __shared__ __align__(16) float Ws[2][TE][KK];

    const int tid = threadIdx.x;
    const int jg  = tid & 3;
    const int rg  = tid >> 2;            // 0..63 -> rows rg and rg+64
    const int jbase = jg * 8;
    const int row0 = blockIdx.x * ROWS_PER_BLK;
    const float* Xg = X + (size_t)row0 * EE;

    // accumulators, initialized with bias
    unsigned long long acc[2][4];
    {
#pragma unroll
        for (int u = 0; u < 4; u++) {
            unsigned long long bv = pack2(bias[jbase + 2 * u], bias[jbase + 2 * u + 1]);
            acc[0][u] = bv;
            acc[1][u] = bv;
        }
    }

    // tile loader: X 128x32 floats = 1024 16B chunks (4/thread); W 32x32 = 256 chunks
    auto load_tile = [&](int bi, int e0) {
#pragma unroll
        for (int l = 0; l < 4; l++) {
            int id  = tid + l * 256;
            int r   = id >> 3;
            int ch  = id & 7;
            cp_async16(&Xs[bi][r][ch * 4], Xg + (size_t)r * EE + e0 + ch * 4);
        }
        {
            int e  = tid >> 3;
            int j4 = (tid & 7) * 4;
            cp_async16(&Ws[bi][e][j4], W + (size_t)(e0 + e) * KK + j4);
        }
    };

    load_tile(0, 0);
    CP_COMMIT();

    const int NT = EE / TE;   // 64 tiles
    for (int t = 0; t < NT; t++) {
        const int bi = t & 1;
        if (t + 1 < NT) {
            load_tile(bi ^ 1, (t + 1) * TE);
            CP_COMMIT();
            CP_WAIT1();
        } else {
            CP_WAIT0();
        }
        __syncthreads();

#pragma unroll
        for (int e = 0; e < TE; e++) {
            unsigned long long w[4];
#pragma unroll
            for (int u = 0; u < 4; u++)
                w[u] = *(const unsigned long long*)&Ws[bi][e][jbase + 2 * u];
            float x0 = Xs[bi][rg][e];
            float x1 = Xs[bi][rg + 64][e];
            unsigned long long xx0 = pack2(x0, x0);
            unsigned long long xx1 = pack2(x1, x1);
#pragma unroll
            for (int u = 0; u < 4; u++) {
                ffma2(acc[0][u], xx0, w[u]);
                ffma2(acc[1][u], xx1, w[u]);
            }
        }
        __syncthreads();   // protect buffer bi before it is refilled at t+2
    }

    float* out = g_logits + (size_t)row0 * KK;
#pragma unroll
    for (int r = 0; r < 2; r++) {
        int row = rg + r * 64;
#pragma unroll
        for (int u = 0; u < 4; u++)
            *(unsigned long long*)&out[row * KK + jbase + 2 * u] = acc[r][u];
    }
}

// ---------------------------------------------------------------------------
// CRF kernel: one warp per batch. lane = tag j.
// Probability-space forward recurrence, f32x2 matvec, depth-2 emission
// prefetch with exp off the critical chain.
// ---------------------------------------------------------------------------
__global__ void __launch_bounds__(32) crf_kernel(const int* __restrict__ y,
                                                 const unsigned int* __restrict__ mask,
                                                 const float* __restrict__ trans,
                                                 const float* __restrict__ startT,
                                                 const float* __restrict__ endT) {
    const int b = blockIdx.x;
    const int j = threadIdx.x;
    const float* L = g_logits + (size_t)b * TT * KK;
    const unsigned int* mk = mask + b * TT;
    const int* yb = y + b * TT;

    // ---- sequence length (mask is a prefix) ----
    int cnt = 0;
    for (int t = j; t < TT; t += 32) cnt += (mk[t] != 0u);
#pragma unroll
    for (int o = 16; o; o >>= 1) cnt += __shfl_xor_sync(0xffffffffu, cnt, o);
    const int len = cnt;

    // ---- joint (numerator) path score ----
    float num = 0.f;
    for (int t = j; t < TT; t += 32) {
        if (mk[t] != 0u) {
            int yt = yb[t];
            num += L[t * KK + yt];
            if (t > 0) num += trans[yb[t - 1] * KK + yt];
        }
    }
#pragma unroll
    for (int o = 16; o; o >>= 1) num += __shfl_xor_sync(0xffffffffu, num, o);
    if (j == 0) num += startT[yb[0]] + endT[yb[len - 1]];

    // ---- forward algorithm (denominator), probability space ----
    // ET2[k] = (exp(trans[2k][j]), exp(trans[2k+1][j]))
    unsigned long long ET2[KK / 2];
#pragma unroll
    for (int k = 0; k < KK / 2; k++)
        ET2[k] = pack2(__expf(trans[(2 * k) * KK + j]),
                       __expf(trans[(2 * k + 1) * KK + j]));
    const float ej = endT[j];

    __shared__ __align__(16) float psh[2][KK];

    float a0 = startT[j] + L[j];
    float m = a0;
#pragma unroll
    for (int o = 16; o; o >>= 1) m = fmaxf(m, __shfl_xor_sync(0xffffffffu, m, o));
    float p = __expf(a0 - m);
    float s = m;
    psh[0][j] = p;
    __syncwarp();

    // depth-2 emission prefetch: ex = exp(L[t]), exn = exp(L[t+1]), xraw = L[t+2]
    float ex  = (len > 1) ? __expf(L[1 * KK + j]) : 1.f;
    float exn = (len > 2) ? __expf(L[2 * KK + j]) : 1.f;
    float xraw = (len > 3) ? L[3 * KK + j] : 0.f;

    int buf = 0;
    for (int t = 1; t < len; t++) {
        // matvec r[j] = sum_i p[i] * exp(trans[i][j]) via packed f32x2
        const ulonglong2* pb2 = (const ulonglong2*)psh[buf];
        unsigned long long A0 = 0, A1 = 0, A2 = 0, A3 = 0;
#pragma unroll
        for (int mm = 0; mm < 4; mm++) {
            ulonglong2 v0 = pb2[2 * mm];
            ulonglong2 v1 = pb2[2 * mm + 1];
            ffma2(A0, v0.x, ET2[4 * mm + 0]);
            ffma2(A1, v0.y, ET2[4 * mm + 1]);
            ffma2(A2, v1.x, ET2[4 * mm + 2]);
            ffma2(A3, v1.y, ET2[4 * mm + 3]);
        }
        float f0, f1, f2, f3, f4, f5, f6, f7;
        unpack2(f0, f1, A0); unpack2(f2, f3, A1);
        unpack2(f4, f5, A2); unpack2(f6, f7, A3);
        float r = ((f0 + f1) + (f2 + f3)) + ((f4 + f5) + (f6 + f7));

        p = r * ex;

        // advance prefetch pipeline (off the critical chain)
        ex  = exn;
        exn = __expf(xraw);
        if (t + 4 < len) xraw = L[(t + 4) * KK + j];

        if ((t & 7) == 0) {  // renormalize every 8 steps (overflow-safe window)
            float mx = p;
#pragma unroll
            for (int o = 16; o; o >>= 1)
                mx = fmaxf(mx, __shfl_xor_sync(0xffffffffu, mx, o));
            s += __logf(mx);
            p *= __frcp_rn(mx);
        }
        buf ^= 1;
        psh[buf][j] = p;
        __syncwarp();
    }

    float q = p * __expf(ej);
#pragma unroll
    for (int o = 16; o; o >>= 1) q += __shfl_xor_sync(0xffffffffu, q, o);
    float den = s + __logf(q);

    if (j == 0) g_partial[b] = num - den;
}

// ---------------------------------------------------------------------------
// Final reduction: loss = -sum_b (num_b - den_b)
// ---------------------------------------------------------------------------
__global__ void __launch_bounds__(32) reduce_kernel(float* __restrict__ out) {
    int j = threadIdx.x;
    float v = g_partial[j] + g_partial[j + 32];
#pragma unroll
    for (int o = 16; o; o >>= 1) v += __shfl_xor_sync(0xffffffffu, v, o);
    if (j == 0) out[0] = -v;
}

// ---------------------------------------------------------------------------
extern "C" void kernel_launch(void* const* d_in, const int* in_sizes, int n_in,
                              void* d_out, int out_size) {
    const float*         X     = (const float*)d_in[0];
    const int*           y     = (const int*)d_in[1];
    const unsigned int*  mask  = (const unsigned int*)d_in[2];
    const float*         W     = (const float*)d_in[3];
    const float*         bias  = (const float*)d_in[4];
    const float*         trans = (const float*)d_in[5];
    const float*         stt   = (const float*)d_in[6];
    const float*         endt  = (const float*)d_in[7];
    float* out = (float*)d_out;

    gemm_kernel<<<(BB * TT) / ROWS_PER_BLK, 256>>>(X, W, bias);
    crf_kernel<<<BB, 32>>>(y, mask, trans, stt, endt);
    reduce_kernel<<<1, 32>>>(out);
}

// round 5
// speedup vs baseline: 1.6648x; 1.4015x over previous
#include <cuda_runtime.h>
#include <cuda_bf16.h>
#include <cstdint>

// Problem constants
#define BB 64
#define TT 512
#define EE 2048
#define KK 32
#define MM (BB * TT)

// Scratch (device globals: no allocation allowed)
__device__ float g_logits[MM * KK];          // 4 MB raw logits
__device__ float g_exp[MM * KK];             // 4 MB exp(logits)
__device__ float g_partial[BB];

// ---------------------------------------------------------------------------
// helpers
// ---------------------------------------------------------------------------
static __device__ __forceinline__ unsigned long long pack2(float lo, float hi) {
    unsigned long long d;
    asm("mov.b64 %0, {%1, %2};" : "=l"(d) : "f"(lo), "f"(hi));
    return d;
}
static __device__ __forceinline__ void ffma2(unsigned long long& acc,
                                             unsigned long long a,
                                             unsigned long long b) {
    asm("fma.rn.f32x2 %0, %1, %2, %0;" : "+l"(acc) : "l"(a), "l"(b));
}
static __device__ __forceinline__ void addf2(unsigned long long& d,
                                             unsigned long long a,
                                             unsigned long long b) {
    asm("add.rn.f32x2 %0, %1, %2;" : "=l"(d) : "l"(a), "l"(b));
}
static __device__ __forceinline__ void unpack2(float& lo, float& hi,
                                               unsigned long long v) {
    asm("mov.b64 {%0, %1}, %2;" : "=f"(lo), "=f"(hi) : "l"(v));
}
static __device__ __forceinline__ uint32_t to_tf32(float f) {
    uint32_t r;
    asm("cvt.rna.tf32.f32 %0, %1;" : "=r"(r) : "f"(f));
    return r;
}
static __device__ __forceinline__ void mma_tf32(float& c0, float& c1,
                                                float& c2, float& c3,
                                                uint32_t a0, uint32_t a1,
                                                uint32_t a2, uint32_t a3,
                                                uint32_t b0, uint32_t b1) {
    asm volatile(
        "mma.sync.aligned.m16n8k8.row.col.f32.tf32.tf32.f32 "
        "{%0,%1,%2,%3}, {%4,%5,%6,%7}, {%8,%9}, {%0,%1,%2,%3};\n"
        : "+f"(c0), "+f"(c1), "+f"(c2), "+f"(c3)
        : "r"(a0), "r"(a1), "r"(a2), "r"(a3), "r"(b0), "r"(b1));
}
static __device__ __forceinline__ void cp_async16(void* dst, const void* src) {
    unsigned sdst = (unsigned)__cvta_generic_to_shared(dst);
    asm volatile("cp.async.cg.shared.global [%0], [%1], 16;\n"
                 :: "r"(sdst), "l"(src));
}
#define CP_COMMIT() asm volatile("cp.async.commit_group;\n" ::: "memory")
#define CP_WAIT0()  asm volatile("cp.async.wait_group 0;\n" ::: "memory")
#define CP_WAIT1()  asm volatile("cp.async.wait_group 1;\n" ::: "memory")

// ---------------------------------------------------------------------------
// GEMM: logits = X @ W + b via mma.sync tf32; also writes exp(logits).
//   M = 32768, E = 2048, N(out) = 32
// 256 CTAs x 256 threads (8 warps), 128 rows/CTA.
// Warp w: output rows [16w, 16w+16), all 32 cols -> 4 mma fragments.
// K tiled by 32, double-buffered cp.async.
// ---------------------------------------------------------------------------
#define TE 32
#define ROWS_PER_BLK 128
#define XPITCH 36   // 144B rows: 16B-aligned, (4r+c) banks conflict-free

__global__ void __launch_bounds__(256) gemm_kernel(const float* __restrict__ X,
                                                   const float* __restrict__ W,
                                                   const float* __restrict__ bias) {
    __shared__ __align__(16) float Xs[2][ROWS_PER_BLK][XPITCH];
    __shared__ __align__(16) float Ws[2][TE][KK];

    const int tid = threadIdx.x;
    const int wid = tid >> 5;
    const int lid = tid & 31;
    const int qr  = lid >> 2;   // 0..7  ("t/4" in mma fragment layout)
    const int c   = lid & 3;    // 0..3  ("t%4")
    const int rw  = wid * 16;
    const int row0 = blockIdx.x * ROWS_PER_BLK;
    const float* Xg = X + (size_t)row0 * EE;

    float acc[4][4];   // [n-fragment][c0..c3]
#pragma unroll
    for (int nf = 0; nf < 4; nf++)
#pragma unroll
        for (int u = 0; u < 4; u++) acc[nf][u] = 0.f;

    auto load_tile = [&](int bi, int e0) {
#pragma unroll
        for (int l = 0; l < 4; l++) {
            int id = tid + l * 256;
            int r  = id >> 3;
            int ch = id & 7;
            cp_async16(&Xs[bi][r][ch * 4], Xg + (size_t)r * EE + e0 + ch * 4);
        }
        {
            int e  = tid >> 3;
            int j4 = (tid & 7) * 4;
            cp_async16(&Ws[bi][e][j4], W + (size_t)(e0 + e) * KK + j4);
        }
    };

    load_tile(0, 0);
    CP_COMMIT();

    const int NT = EE / TE;   // 64
    for (int t = 0; t < NT; t++) {
        const int bi = t & 1;
        if (t + 1 < NT) {
            load_tile(bi ^ 1, (t + 1) * TE);
            CP_COMMIT();
            CP_WAIT1();
        } else {
            CP_WAIT0();
        }
        __syncthreads();

#pragma unroll
        for (int ks = 0; ks < 4; ks++) {
            const int k0 = ks * 8;
            uint32_t a0 = to_tf32(Xs[bi][rw + qr][k0 + c]);
            uint32_t a1 = to_tf32(Xs[bi][rw + qr + 8][k0 + c]);
            uint32_t a2 = to_tf32(Xs[bi][rw + qr][k0 + c + 4]);
            uint32_t a3 = to_tf32(Xs[bi][rw + qr + 8][k0 + c + 4]);
#pragma unroll
            for (int nf = 0; nf < 4; nf++) {
                uint32_t b0 = to_tf32(Ws[bi][k0 + c][nf * 8 + qr]);
                uint32_t b1 = to_tf32(Ws[bi][k0 + c + 4][nf * 8 + qr]);
                mma_tf32(acc[nf][0], acc[nf][1], acc[nf][2], acc[nf][3],
                         a0, a1, a2, a3, b0, b1);
            }
        }
        __syncthreads();
    }

    // epilogue: add bias, write logits and exp(logits)
    float bv0[4], bv1[4];
#pragma unroll
    for (int nf = 0; nf < 4; nf++) {
        bv0[nf] = __ldg(bias + nf * 8 + 2 * c);
        bv1[nf] = __ldg(bias + nf * 8 + 2 * c + 1);
    }
    const int rowa = row0 + rw + qr;
    const int rowb = rowa + 8;
    float* loA = g_logits + (size_t)rowa * KK;
    float* loB = g_logits + (size_t)rowb * KK;
    float* eoA = g_exp + (size_t)rowa * KK;
    float* eoB = g_exp + (size_t)rowb * KK;
#pragma unroll
    for (int nf = 0; nf < 4; nf++) {
        int j0 = nf * 8 + 2 * c;
        float2 va = make_float2(acc[nf][0] + bv0[nf], acc[nf][1] + bv1[nf]);
        float2 vb = make_float2(acc[nf][2] + bv0[nf], acc[nf][3] + bv1[nf]);
        *(float2*)(loA + j0) = va;
        *(float2*)(loB + j0) = vb;
        *(float2*)(eoA + j0) = make_float2(__expf(va.x), __expf(va.y));
        *(float2*)(eoB + j0) = make_float2(__expf(vb.x), __expf(vb.y));
    }
}

// ---------------------------------------------------------------------------
// CRF kernel: one warp per batch. lane = tag j.
// Probability-space forward recurrence; emissions pre-exponentiated.
// ---------------------------------------------------------------------------
__global__ void __launch_bounds__(32) crf_kernel(const int* __restrict__ y,
                                                 const unsigned int* __restrict__ mask,
                                                 const float* __restrict__ trans,
                                                 const float* __restrict__ startT,
                                                 const float* __restrict__ endT) {
    const int b = blockIdx.x;
    const int j = threadIdx.x;
    const float* L  = g_logits + (size_t)b * TT * KK;
    const float* EL = g_exp    + (size_t)b * TT * KK;
    const unsigned int* mk = mask + b * TT;
    const int* yb = y + b * TT;

    // ---- sequence length (mask is a prefix) ----
    int cnt = 0;
    for (int t = j; t < TT; t += 32) cnt += (mk[t] != 0u);
#pragma unroll
    for (int o = 16; o; o >>= 1) cnt += __shfl_xor_sync(0xffffffffu, cnt, o);
    const int len = cnt;

    // ---- joint (numerator) path score ----
    float num = 0.f;
    for (int t = j; t < TT; t += 32) {
        if (mk[t] != 0u) {
            int yt = yb[t];
            num += L[t * KK + yt];
            if (t > 0) num += trans[yb[t - 1] * KK + yt];
        }
    }
#pragma unroll
    for (int o = 16; o; o >>= 1) num += __shfl_xor_sync(0xffffffffu, num, o);
    if (j == 0) num += startT[yb[0]] + endT[yb[len - 1]];

    // ---- forward algorithm (denominator), probability space ----
    unsigned long long ET2[KK / 2];   // (exp(trans[2k][j]), exp(trans[2k+1][j]))
#pragma unroll
    for (int k = 0; k < KK / 2; k++)
        ET2[k] = pack2(__expf(trans[(2 * k) * KK + j]),
                       __expf(trans[(2 * k + 1) * KK + j]));
    const float ej = endT[j];

    __shared__ __align__(16) float psh[2][KK];

    float a0 = startT[j] + L[j];
    float m = a0;
#pragma unroll
    for (int o = 16; o; o >>= 1) m = fmaxf(m, __shfl_xor_sync(0xffffffffu, m, o));
    float p = __expf(a0 - m);
    float s = m;
    psh[0][j] = p;
    __syncwarp();

    // rolling emission prefetch (already exponentiated)
    float e1 = (len > 1) ? EL[1 * KK + j] : 1.f;
    float e2 = (len > 2) ? EL[2 * KK + j] : 1.f;
    float e3 = (len > 3) ? EL[3 * KK + j] : 1.f;
    float e4 = (len > 4) ? EL[4 * KK + j] : 1.f;

    int buf = 0;
    for (int t = 1; t < len; t++) {
        const ulonglong2* pb2 = (const ulonglong2*)psh[buf];
        unsigned long long A0 = 0, A1 = 0, A2 = 0, A3 = 0;
#pragma unroll
        for (int mm = 0; mm < 4; mm++) {
            ulonglong2 v0 = pb2[2 * mm];
            ulonglong2 v1 = pb2[2 * mm + 1];
            ffma2(A0, v0.x, ET2[4 * mm + 0]);
            ffma2(A1, v0.y, ET2[4 * mm + 1]);
            ffma2(A2, v1.x, ET2[4 * mm + 2]);
            ffma2(A3, v1.y, ET2[4 * mm + 3]);
        }
        unsigned long long S0, S1, S2;
        addf2(S0, A0, A1);
        addf2(S1, A2, A3);
        addf2(S2, S0, S1);
        float rl, rh;
        unpack2(rl, rh, S2);
        p = (rl + rh) * e1;

        e1 = e2; e2 = e3; e3 = e4;
        e4 = (t + 4 < len) ? EL[(t + 4) * KK + j] : 1.f;

        if ((t & 7) == 0) {
            // renorm by power-of-2 of warp-max (p > 0: uint order == float order)
            unsigned mxb = __reduce_max_sync(0xffffffffu, __float_as_uint(p));
            unsigned e = mxb >> 23;
            p *= __uint_as_float((254u - e) << 23);        // exact 2^(127-e)
            s += (float)((int)e - 127) * 0.6931471805599453f;
        }
        buf ^= 1;
        psh[buf][j] = p;
        __syncwarp();
    }

    float q = p * __expf(ej);
#pragma unroll
    for (int o = 16; o; o >>= 1) q += __shfl_xor_sync(0xffffffffu, q, o);
    float den = s + __logf(q);

    if (j == 0) g_partial[b] = num - den;
}

// ---------------------------------------------------------------------------
// Final reduction: loss = -sum_b (num_b - den_b)
// ---------------------------------------------------------------------------
__global__ void __launch_bounds__(32) reduce_kernel(float* __restrict__ out) {
    int j = threadIdx.x;
    float v = g_partial[j] + g_partial[j + 32];
#pragma unroll
    for (int o = 16; o; o >>= 1) v += __shfl_xor_sync(0xffffffffu, v, o);
    if (j == 0) out[0] = -v;
}

// ---------------------------------------------------------------------------
extern "C" void kernel_launch(void* const* d_in, const int* in_sizes, int n_in,
                              void* d_out, int out_size) {
    const float*         X     = (const float*)d_in[0];
    const int*           y     = (const int*)d_in[1];
    const unsigned int*  mask  = (const unsigned int*)d_in[2];
    const float*         W     = (const float*)d_in[3];
    const float*         bias  = (const float*)d_in[4];
    const float*         trans = (const float*)d_in[5];
    const float*         stt   = (const float*)d_in[6];
    const float*         endt  = (const float*)d_in[7];
    float* out = (float*)d_out;

    gemm_kernel<<<MM / ROWS_PER_BLK, 256>>>(X, W, bias);
    crf_kernel<<<BB, 32>>>(y, mask, trans, stt, endt);
    reduce_kernel<<<1, 32>>>(out);
}

// round 6
// speedup vs baseline: 1.8329x; 1.1010x over previous
#include <cuda_runtime.h>
#include <cuda_bf16.h>
#include <cstdint>

// Problem constants
#define BB 64
#define TT 512
#define EE 2048
#define KK 32
#define MM (BB * TT)

// Scratch (device globals: no allocation allowed)
__device__ float g_logits[MM * KK];          // 4 MB raw logits
__device__ float g_exp[MM * KK];             // 4 MB exp(logits)
__device__ float g_Wt[KK * EE];              // W transposed: [n][e]
__device__ float g_partial[BB];

// ---------------------------------------------------------------------------
// helpers
// ---------------------------------------------------------------------------
static __device__ __forceinline__ unsigned long long pack2(float lo, float hi) {
    unsigned long long d;
    asm("mov.b64 %0, {%1, %2};" : "=l"(d) : "f"(lo), "f"(hi));
    return d;
}
static __device__ __forceinline__ void ffma2(unsigned long long& acc,
                                             unsigned long long a,
                                             unsigned long long b) {
    asm("fma.rn.f32x2 %0, %1, %2, %0;" : "+l"(acc) : "l"(a), "l"(b));
}
static __device__ __forceinline__ void addf2(unsigned long long& d,
                                             unsigned long long a,
                                             unsigned long long b) {
    asm("add.rn.f32x2 %0, %1, %2;" : "=l"(d) : "l"(a), "l"(b));
}
static __device__ __forceinline__ void unpack2(float& lo, float& hi,
                                               unsigned long long v) {
    asm("mov.b64 {%0, %1}, %2;" : "=f"(lo), "=f"(hi) : "l"(v));
}
static __device__ __forceinline__ void mma_tf32(float& c0, float& c1,
                                                float& c2, float& c3,
                                                uint32_t a0, uint32_t a1,
                                                uint32_t a2, uint32_t a3,
                                                uint32_t b0, uint32_t b1) {
    asm volatile(
        "mma.sync.aligned.m16n8k8.row.col.f32.tf32.tf32.f32 "
        "{%0,%1,%2,%3}, {%4,%5,%6,%7}, {%8,%9}, {%0,%1,%2,%3};\n"
        : "+f"(c0), "+f"(c1), "+f"(c2), "+f"(c3)
        : "r"(a0), "r"(a1), "r"(a2), "r"(a3), "r"(b0), "r"(b1));
}
static __device__ __forceinline__ void cp_async16(void* dst, const void* src) {
    unsigned sdst = (unsigned)__cvta_generic_to_shared(dst);
    asm volatile("cp.async.cg.shared.global [%0], [%1], 16;\n"
                 :: "r"(sdst), "l"(src));
}
#define CP_COMMIT() asm volatile("cp.async.commit_group;\n" ::: "memory")
#define CP_WAIT0()  asm volatile("cp.async.wait_group 0;\n" ::: "memory")
#define CP_WAIT1()  asm volatile("cp.async.wait_group 1;\n" ::: "memory")

// ---------------------------------------------------------------------------
// W transpose pre-pass: g_Wt[n][e] = W[e][n], via smem tile (coalesced both ways)
// grid 32 x 256 threads: each block handles 64 e-rows.
// ---------------------------------------------------------------------------
__global__ void __launch_bounds__(256) wtrans_kernel(const float* __restrict__ W) {
    __shared__ float s[64][33];
    const int tid = threadIdx.x;
    const int e0 = blockIdx.x * 64;
#pragma unroll
    for (int l = 0; l < 8; l++) {
        int idx = tid + l * 256;           // 0..2047
        int ep = idx >> 5, n = idx & 31;
        s[ep][n] = W[(size_t)(e0 + ep) * KK + n];
    }
    __syncthreads();
#pragma unroll
    for (int l = 0; l < 8; l++) {
        int idx = tid + l * 256;
        int n = idx >> 6, ep = idx & 63;
        g_Wt[(size_t)n * EE + e0 + ep] = s[ep][n];
    }
}

// ---------------------------------------------------------------------------
// GEMM: logits = X @ W + b via mma.sync tf32 (raw fp32 bits, HW-truncated).
//   M = 32768, E = 2048, N = 32
// 512 CTAs x 128 threads (4 warps), 64 rows/CTA; warp: 16 rows x 32 cols.
// K tiled by 32, double-buffered cp.async. k-permuted fragments -> LDS.64.
// ---------------------------------------------------------------------------
#define TE 32
#define RPB 64
#define XPITCH 36   // 144B rows: 16B-aligned, 2-phase conflict-free LDS.64

__global__ void __launch_bounds__(128) gemm_kernel(const float* __restrict__ X,
                                                   const float* __restrict__ bias) {
    __shared__ __align__(16) float Xs[2][RPB][XPITCH];
    __shared__ __align__(16) float Ws[2][KK][XPITCH];

    const int tid = threadIdx.x;
    const int wid = tid >> 5;
    const int lid = tid & 31;
    const int qr  = lid >> 2;   // 0..7
    const int c   = lid & 3;    // 0..3
    const int rw  = wid * 16;
    const int row0 = blockIdx.x * RPB;
    const float* Xg = X + (size_t)row0 * EE;

    float acc[4][4];
#pragma unroll
    for (int nf = 0; nf < 4; nf++)
#pragma unroll
        for (int u = 0; u < 4; u++) acc[nf][u] = 0.f;

    auto load_tile = [&](int bi, int e0) {
#pragma unroll
        for (int l = 0; l < 4; l++) {        // X: 64 rows x 32 = 512 float4
            int id = tid + l * 128;
            int r  = id >> 3;
            int ch = id & 7;
            cp_async16(&Xs[bi][r][ch * 4], Xg + (size_t)r * EE + e0 + ch * 4);
        }
#pragma unroll
        for (int l = 0; l < 2; l++) {        // Wt: 32 rows x 32 = 256 float4
            int id = tid + l * 128;
            int n  = id >> 3;
            int ch = id & 7;
            cp_async16(&Ws[bi][n][ch * 4], g_Wt + (size_t)n * EE + e0 + ch * 4);
        }
    };

    load_tile(0, 0);
    CP_COMMIT();

    const int NT = EE / TE;   // 64
    for (int t = 0; t < NT; t++) {
        const int bi = t & 1;
        if (t + 1 < NT) {
            load_tile(bi ^ 1, (t + 1) * TE);
            CP_COMMIT();
            CP_WAIT1();
        } else {
            CP_WAIT0();
        }
        __syncthreads();

        // k-permutation: mma k-lane c <-> physical k0+2c; c+4 <-> k0+2c+1
#pragma unroll
        for (int ks = 0; ks < 4; ks++) {
            const int kp = ks * 8 + 2 * c;
            float2 xa = *(const float2*)&Xs[bi][rw + qr][kp];
            float2 xb = *(const float2*)&Xs[bi][rw + qr + 8][kp];
            uint32_t a0 = __float_as_uint(xa.x);
            uint32_t a2 = __float_as_uint(xa.y);
            uint32_t a1 = __float_as_uint(xb.x);
            uint32_t a3 = __float_as_uint(xb.y);
#pragma unroll
            for (int nf = 0; nf < 4; nf++) {
                float2 wv = *(const float2*)&Ws[bi][nf * 8 + qr][kp];
                mma_tf32(acc[nf][0], acc[nf][1], acc[nf][2], acc[nf][3],
                         a0, a1, a2, a3,
                         __float_as_uint(wv.x), __float_as_uint(wv.y));
            }
        }
        __syncthreads();
    }

    // epilogue: add bias, write logits and exp(logits)
    float bv0[4], bv1[4];
#pragma unroll
    for (int nf = 0; nf < 4; nf++) {
        bv0[nf] = __ldg(bias + nf * 8 + 2 * c);
        bv1[nf] = __ldg(bias + nf * 8 + 2 * c + 1);
    }
    const int rowa = row0 + rw + qr;
    const int rowb = rowa + 8;
    float* loA = g_logits + (size_t)rowa * KK;
    float* loB = g_logits + (size_t)rowb * KK;
    float* eoA = g_exp + (size_t)rowa * KK;
    float* eoB = g_exp + (size_t)rowb * KK;
#pragma unroll
    for (int nf = 0; nf < 4; nf++) {
        int j0 = nf * 8 + 2 * c;
        float2 va = make_float2(acc[nf][0] + bv0[nf], acc[nf][1] + bv1[nf]);
        float2 vb = make_float2(acc[nf][2] + bv0[nf], acc[nf][3] + bv1[nf]);
        *(float2*)(loA + j0) = va;
        *(float2*)(loB + j0) = vb;
        *(float2*)(eoA + j0) = make_float2(__expf(va.x), __expf(va.y));
        *(float2*)(eoB + j0) = make_float2(__expf(vb.x), __expf(vb.y));
    }
}

// ---------------------------------------------------------------------------
// CRF kernel: one warp per batch. lane = tag j.
// Probability-space forward recurrence; emissions pre-exponentiated;
// renormalization off the critical path (scale folded into next emission).
// ---------------------------------------------------------------------------
__global__ void __launch_bounds__(32) crf_kernel(const int* __restrict__ y,
                                                 const unsigned int* __restrict__ mask,
                                                 const float* __restrict__ trans,
                                                 const float* __restrict__ startT,
                                                 const float* __restrict__ endT) {
    const int b = blockIdx.x;
    const int j = threadIdx.x;
    const float* L  = g_logits + (size_t)b * TT * KK;
    const float* EL = g_exp    + (size_t)b * TT * KK;
    const unsigned int* mk = mask + b * TT;
    const int* yb = y + b * TT;

    // ---- sequence length (mask is a prefix) ----
    int cnt = 0;
    for (int t = j; t < TT; t += 32) cnt += (mk[t] != 0u);
#pragma unroll
    for (int o = 16; o; o >>= 1) cnt += __shfl_xor_sync(0xffffffffu, cnt, o);
    const int len = cnt;

    // ---- joint (numerator) path score ----
    float num = 0.f;
    for (int t = j; t < TT; t += 32) {
        if (mk[t] != 0u) {
            int yt = yb[t];
            num += L[t * KK + yt];
            if (t > 0) num += trans[yb[t - 1] * KK + yt];
        }
    }
#pragma unroll
    for (int o = 16; o; o >>= 1) num += __shfl_xor_sync(0xffffffffu, num, o);
    if (j == 0) num += startT[yb[0]] + endT[yb[len - 1]];

    // ---- forward algorithm (denominator), probability space ----
    unsigned long long ET2[KK / 2];   // (exp(trans[2k][j]), exp(trans[2k+1][j]))
#pragma unroll
    for (int k = 0; k < KK / 2; k++)
        ET2[k] = pack2(__expf(trans[(2 * k) * KK + j]),
                       __expf(trans[(2 * k + 1) * KK + j]));
    const float ej = endT[j];

    __shared__ __align__(16) float psh[2][KK];

    float a0 = startT[j] + L[j];
    float m = a0;
#pragma unroll
    for (int o = 16; o; o >>= 1) m = fmaxf(m, __shfl_xor_sync(0xffffffffu, m, o));
    float p = __expf(a0 - m);
    float s = m;
    psh[0][j] = p;
    __syncwarp();

    // rolling emission prefetch (already exponentiated)
    float e1 = EL[min(1, TT - 1) * KK + j];
    float e2 = EL[min(2, TT - 1) * KK + j];
    float e3 = EL[min(3, TT - 1) * KK + j];
    float e4 = EL[min(4, TT - 1) * KK + j];

    float sc = 1.f;   // pending renorm scale (applied one step later)
    int buf = 0;
#pragma unroll 2
    for (int t = 1; t < len; t++) {
        const ulonglong2* pb2 = (const ulonglong2*)psh[buf];
        unsigned long long A0 = 0, A1 = 0, A2 = 0, A3 = 0;
#pragma unroll
        for (int mm = 0; mm < 4; mm++) {
            ulonglong2 v0 = pb2[2 * mm];
            ulonglong2 v1 = pb2[2 * mm + 1];
            ffma2(A0, v0.x, ET2[4 * mm + 0]);
            ffma2(A1, v0.y, ET2[4 * mm + 1]);
            ffma2(A2, v1.x, ET2[4 * mm + 2]);
            ffma2(A3, v1.y, ET2[4 * mm + 3]);
        }
        unsigned long long S0, S1, S2;
        addf2(S0, A0, A1);
        addf2(S1, A2, A3);
        addf2(S2, S0, S1);
        float rl, rh;
        unpack2(rl, rh, S2);
        p = (rl + rh) * (e1 * sc);
        sc = 1.f;

        e1 = e2; e2 = e3; e3 = e4;
        e4 = EL[min(t + 4, TT - 1) * KK + j];

        buf ^= 1;
        psh[buf][j] = p;
        __syncwarp();

        if ((t & 7) == 0) {
            // scale computed AFTER the store; overlaps next step's matvec.
            // p > 0 so uint order == float order.
            unsigned mxb = __reduce_max_sync(0xffffffffu, __float_as_uint(p));
            unsigned e = mxb >> 23;
            sc = __uint_as_float((254u - e) << 23);        // exact 2^(127-e)
            s += (float)((int)e - 127) * 0.6931471805599453f;
        }
    }
    p *= sc;   // pending scale if loop ended right after a renorm point

    float q = p * __expf(ej);
#pragma unroll
    for (int o = 16; o; o >>= 1) q += __shfl_xor_sync(0xffffffffu, q, o);
    float den = s + __logf(q);

    if (j == 0) g_partial[b] = num - den;
}

// ---------------------------------------------------------------------------
// Final reduction: loss = -sum_b (num_b - den_b)
// ---------------------------------------------------------------------------
__global__ void __launch_bounds__(32) reduce_kernel(float* __restrict__ out) {
    int j = threadIdx.x;
    float v = g_partial[j] + g_partial[j + 32];
#pragma unroll
    for (int o = 16; o; o >>= 1) v += __shfl_xor_sync(0xffffffffu, v, o);
    if (j == 0) out[0] = -v;
}

// ---------------------------------------------------------------------------
extern "C" void kernel_launch(void* const* d_in, const int* in_sizes, int n_in,
                              void* d_out, int out_size) {
    const float*         X     = (const float*)d_in[0];
    const int*           y     = (const int*)d_in[1];
    const unsigned int*  mask  = (const unsigned int*)d_in[2];
    const float*         W     = (const float*)d_in[3];
    const float*         bias  = (const float*)d_in[4];
    const float*         trans = (const float*)d_in[5];
    const float*         stt   = (const float*)d_in[6];
    const float*         endt  = (const float*)d_in[7];
    float* out = (float*)d_out;

    wtrans_kernel<<<EE / 64, 256>>>(W);
    gemm_kernel<<<MM / RPB, 128>>>(X, bias);
    crf_kernel<<<BB, 32>>>(y, mask, trans, stt, endt);
    reduce_kernel<<<1, 32>>>(out);
}

// round 7
// speedup vs baseline: 1.9883x; 1.0848x over previous
#include <cuda_runtime.h>
#include <cuda_bf16.h>
#include <cstdint>

// Problem constants
#define BB 64
#define TT 512
#define EE 2048
#define KK 32
#define MM (BB * TT)

// Scratch (device globals: no allocation allowed)
__device__ float g_logits[MM * KK];          // 4 MB raw logits
__device__ float g_exp[MM * KK];             // 4 MB exp(logits)
__device__ float g_Wt[KK * EE];              // W transposed (tf32-rounded): [n][e]
__device__ float g_partial[BB];
__device__ int   g_done = 0;

// ---------------------------------------------------------------------------
// helpers
// ---------------------------------------------------------------------------
static __device__ __forceinline__ unsigned long long pack2(float lo, float hi) {
    unsigned long long d;
    asm("mov.b64 %0, {%1, %2};" : "=l"(d) : "f"(lo), "f"(hi));
    return d;
}
static __device__ __forceinline__ void ffma2(unsigned long long& acc,
                                             unsigned long long a,
                                             unsigned long long b) {
    asm("fma.rn.f32x2 %0, %1, %2, %0;" : "+l"(acc) : "l"(a), "l"(b));
}
static __device__ __forceinline__ void addf2(unsigned long long& d,
                                             unsigned long long a,
                                             unsigned long long b) {
    asm("add.rn.f32x2 %0, %1, %2;" : "=l"(d) : "l"(a), "l"(b));
}
static __device__ __forceinline__ void unpack2(float& lo, float& hi,
                                               unsigned long long v) {
    asm("mov.b64 {%0, %1}, %2;" : "=f"(lo), "=f"(hi) : "l"(v));
}
static __device__ __forceinline__ float tf32_round(float f) {
    uint32_t r;
    asm("cvt.rna.tf32.f32 %0, %1;" : "=r"(r) : "f"(f));
    return __uint_as_float(r);
}
static __device__ __forceinline__ void mma_tf32(float& c0, float& c1,
                                                float& c2, float& c3,
                                                uint32_t a0, uint32_t a1,
                                                uint32_t a2, uint32_t a3,
                                                uint32_t b0, uint32_t b1) {
    asm volatile(
        "mma.sync.aligned.m16n8k8.row.col.f32.tf32.tf32.f32 "
        "{%0,%1,%2,%3}, {%4,%5,%6,%7}, {%8,%9}, {%0,%1,%2,%3};\n"
        : "+f"(c0), "+f"(c1), "+f"(c2), "+f"(c3)
        : "r"(a0), "r"(a1), "r"(a2), "r"(a3), "r"(b0), "r"(b1));
}
static __device__ __forceinline__ void cp_async16(void* dst, const void* src) {
    unsigned sdst = (unsigned)__cvta_generic_to_shared(dst);
    asm volatile("cp.async.cg.shared.global [%0], [%1], 16;\n"
                 :: "r"(sdst), "l"(src));
}
#define CP_COMMIT() asm volatile("cp.async.commit_group;\n" ::: "memory")
#define CP_WAIT0()  asm volatile("cp.async.wait_group 0;\n" ::: "memory")
#define CP_WAIT1()  asm volatile("cp.async.wait_group 1;\n" ::: "memory")

// ---------------------------------------------------------------------------
// W transpose pre-pass: g_Wt[n][e] = tf32_round(W[e][n])
// ---------------------------------------------------------------------------
__global__ void __launch_bounds__(256) wtrans_kernel(const float* __restrict__ W) {
    __shared__ float s[64][33];
    const int tid = threadIdx.x;
    const int e0 = blockIdx.x * 64;
#pragma unroll
    for (int l = 0; l < 8; l++) {
        int idx = tid + l * 256;
        int ep = idx >> 5, n = idx & 31;
        s[ep][n] = W[(size_t)(e0 + ep) * KK + n];
    }
    __syncthreads();
#pragma unroll
    for (int l = 0; l < 8; l++) {
        int idx = tid + l * 256;
        int n = idx >> 6, ep = idx & 63;
        g_Wt[(size_t)n * EE + e0 + ep] = tf32_round(s[ep][n]);
    }
}

// ---------------------------------------------------------------------------
// GEMM: logits = X @ W + b via mma.sync tf32; writes logits and exp(logits).
//   M = 32768, E = 2048, N = 32
// 256 CTAs x 128 threads (4 warps), 128 rows/CTA; warp: 32 rows x 32 cols.
// X: cp.async smem pipeline (depth 2). W fragments: direct LDG.64 from
// L2-resident g_Wt into registers, one tile ahead. k-permuted frags (LDS.64).
// ---------------------------------------------------------------------------
#define TE 32
#define RPB 128
#define XPITCH 36

__global__ void __launch_bounds__(128) gemm_kernel(const float* __restrict__ X,
                                                   const float* __restrict__ bias) {
    __shared__ __align__(16) float Xs[2][RPB][XPITCH];

    const int tid = threadIdx.x;
    const int wid = tid >> 5;
    const int lid = tid & 31;
    const int qr  = lid >> 2;   // 0..7
    const int c   = lid & 3;    // 0..3
    const int rw2 = wid * 32;
    const int row0 = blockIdx.x * RPB;
    const float* Xg = X + (size_t)row0 * EE;
    const int NT = EE / TE;     // 64

    float acc[2][4][4];
#pragma unroll
    for (int g = 0; g < 2; g++)
#pragma unroll
        for (int nf = 0; nf < 4; nf++)
#pragma unroll
            for (int u = 0; u < 4; u++) acc[g][nf][u] = 0.f;

    auto loadX = [&](int bi, int t) {
        const int e0 = t * TE;
#pragma unroll
        for (int l = 0; l < 8; l++) {     // 128 rows x 8 chunks = 1024 float4
            int id = tid + l * 128;
            int r  = id >> 3;
            int ch = id & 7;
            cp_async16(&Xs[bi][r][ch * 4], Xg + (size_t)r * EE + e0 + ch * 4);
        }
    };
    auto loadB = [&](float2* Bf, int t) {
        const int e0 = t * TE;
#pragma unroll
        for (int ks = 0; ks < 4; ks++)
#pragma unroll
            for (int nf = 0; nf < 4; nf++)
                Bf[ks * 4 + nf] = *(const float2*)(g_Wt +
                    (size_t)(nf * 8 + qr) * EE + e0 + ks * 8 + 2 * c);
    };

    float2 B0f[16], B1f[16];
    loadX(0, 0); CP_COMMIT();
    loadX(1, 1); CP_COMMIT();
    loadB(B0f, 0);

    auto step = [&](int t, float2* Bcur, float2* Bnext) {
        loadB(Bnext, min(t + 1, NT - 1));         // 1 tile ahead (L2 resident)
        if (t < NT - 1) { CP_WAIT1(); } else { CP_WAIT0(); }
        __syncthreads();

        const float (*Xt)[XPITCH] = Xs[t & 1];
#pragma unroll
        for (int ks = 0; ks < 4; ks++) {
            const int kp = ks * 8 + 2 * c;
            float2 x0 = *(const float2*)&Xt[rw2 + qr][kp];
            float2 x1 = *(const float2*)&Xt[rw2 + qr + 8][kp];
            float2 x2 = *(const float2*)&Xt[rw2 + qr + 16][kp];
            float2 x3 = *(const float2*)&Xt[rw2 + qr + 24][kp];
#pragma unroll
            for (int nf = 0; nf < 4; nf++) {
                float2 wv = Bcur[ks * 4 + nf];
                uint32_t b0 = __float_as_uint(wv.x);
                uint32_t b1 = __float_as_uint(wv.y);
                mma_tf32(acc[0][nf][0], acc[0][nf][1], acc[0][nf][2], acc[0][nf][3],
                         __float_as_uint(x0.x), __float_as_uint(x1.x),
                         __float_as_uint(x0.y), __float_as_uint(x1.y), b0, b1);
                mma_tf32(acc[1][nf][0], acc[1][nf][1], acc[1][nf][2], acc[1][nf][3],
                         __float_as_uint(x2.x), __float_as_uint(x3.x),
                         __float_as_uint(x2.y), __float_as_uint(x3.y), b0, b1);
            }
        }
        __syncthreads();
        if (t + 2 < NT) { loadX(t & 1, t + 2); CP_COMMIT(); }
    };

    for (int t = 0; t < NT; t += 2) {
        step(t, B0f, B1f);
        step(t + 1, B1f, B0f);
    }

    // epilogue: add bias, write logits and exp(logits)
    float bv0[4], bv1[4];
#pragma unroll
    for (int nf = 0; nf < 4; nf++) {
        bv0[nf] = __ldg(bias + nf * 8 + 2 * c);
        bv1[nf] = __ldg(bias + nf * 8 + 2 * c + 1);
    }
#pragma unroll
    for (int g = 0; g < 2; g++) {
        const int rowa = row0 + rw2 + qr + g * 16;
        const int rowb = rowa + 8;
        float* loA = g_logits + (size_t)rowa * KK;
        float* loB = g_logits + (size_t)rowb * KK;
        float* eoA = g_exp + (size_t)rowa * KK;
        float* eoB = g_exp + (size_t)rowb * KK;
#pragma unroll
        for (int nf = 0; nf < 4; nf++) {
            int j0 = nf * 8 + 2 * c;
            float2 va = make_float2(acc[g][nf][0] + bv0[nf], acc[g][nf][1] + bv1[nf]);
            float2 vb = make_float2(acc[g][nf][2] + bv0[nf], acc[g][nf][3] + bv1[nf]);
            *(float2*)(loA + j0) = va;
            *(float2*)(loB + j0) = vb;
            *(float2*)(eoA + j0) = make_float2(__expf(va.x), __expf(va.y));
            *(float2*)(eoB + j0) = make_float2(__expf(vb.x), __expf(vb.y));
        }
    }
}

// ---------------------------------------------------------------------------
// CRF kernel: one warp per batch. lane = tag j.
// Probability-space forward recurrence; emissions pre-exponentiated;
// depth-8 emission prefetch; deferred power-of-2 renorm; fused final reduce.
// ---------------------------------------------------------------------------
__global__ void __launch_bounds__(32) crf_kernel(const int* __restrict__ y,
                                                 const unsigned int* __restrict__ mask,
                                                 const float* __restrict__ trans,
                                                 const float* __restrict__ startT,
                                                 const float* __restrict__ endT,
                                                 float* __restrict__ out) {
    const int b = blockIdx.x;
    const int j = threadIdx.x;
    const float* L  = g_logits + (size_t)b * TT * KK;
    const float* EL = g_exp    + (size_t)b * TT * KK;
    const unsigned int* mk = mask + b * TT;
    const int* yb = y + b * TT;

    // ---- sequence length (mask is a prefix) ----
    int cnt = 0;
    for (int t = j; t < TT; t += 32) cnt += (mk[t] != 0u);
#pragma unroll
    for (int o = 16; o; o >>= 1) cnt += __shfl_xor_sync(0xffffffffu, cnt, o);
    const int len = cnt;

    // ---- joint (numerator) path score ----
    float num = 0.f;
    for (int t = j; t < TT; t += 32) {
        if (mk[t] != 0u) {
            int yt = yb[t];
            num += L[t * KK + yt];
            if (t > 0) num += trans[yb[t - 1] * KK + yt];
        }
    }
#pragma unroll
    for (int o = 16; o; o >>= 1) num += __shfl_xor_sync(0xffffffffu, num, o);
    if (j == 0) num += startT[yb[0]] + endT[yb[len - 1]];

    // ---- forward algorithm (denominator), probability space ----
    unsigned long long ET2[KK / 2];   // (exp(trans[2k][j]), exp(trans[2k+1][j]))
#pragma unroll
    for (int k = 0; k < KK / 2; k++)
        ET2[k] = pack2(__expf(trans[(2 * k) * KK + j]),
                       __expf(trans[(2 * k + 1) * KK + j]));
    const float ej = endT[j];

    __shared__ __align__(16) float psh[2][KK];

    float a0 = startT[j] + L[j];
    float m = a0;
#pragma unroll
    for (int o = 16; o; o >>= 1) m = fmaxf(m, __shfl_xor_sync(0xffffffffu, m, o));
    float p = __expf(a0 - m);
    float s = m;
    psh[0][j] = p;
    __syncwarp();

    // depth-8 rolling emission prefetch (already exponentiated)
    float e1 = EL[min(1, TT - 1) * KK + j];
    float e2 = EL[min(2, TT - 1) * KK + j];
    float e3 = EL[min(3, TT - 1) * KK + j];
    float e4 = EL[min(4, TT - 1) * KK + j];
    float e5 = EL[min(5, TT - 1) * KK + j];
    float e6 = EL[min(6, TT - 1) * KK + j];
    float e7 = EL[min(7, TT - 1) * KK + j];
    float e8 = EL[min(8, TT - 1) * KK + j];

    float sc = 1.f;   // pending renorm scale (applied one step later)
    int buf = 0;
#pragma unroll 4
    for (int t = 1; t < len; t++) {
        const ulonglong2* pb2 = (const ulonglong2*)psh[buf];
        unsigned long long A0 = 0, A1 = 0, A2 = 0, A3 = 0;
#pragma unroll
        for (int mm = 0; mm < 4; mm++) {
            ulonglong2 v0 = pb2[2 * mm];
            ulonglong2 v1 = pb2[2 * mm + 1];
            ffma2(A0, v0.x, ET2[4 * mm + 0]);
            ffma2(A1, v0.y, ET2[4 * mm + 1]);
            ffma2(A2, v1.x, ET2[4 * mm + 2]);
            ffma2(A3, v1.y, ET2[4 * mm + 3]);
        }
        unsigned long long S0, S1, S2;
        addf2(S0, A0, A1);
        addf2(S1, A2, A3);
        addf2(S2, S0, S1);
        float rl, rh;
        unpack2(rl, rh, S2);
        p = (rl + rh) * (e1 * sc);
        sc = 1.f;

        e1 = e2; e2 = e3; e3 = e4; e4 = e5;
        e5 = e6; e6 = e7; e7 = e8;
        e8 = EL[min(t + 8, TT - 1) * KK + j];

        buf ^= 1;
        psh[buf][j] = p;
        __syncwarp();

        if ((t & 7) == 0) {
            // scale computed AFTER the store; overlaps next step's matvec.
            unsigned mxb = __reduce_max_sync(0xffffffffu, __float_as_uint(p));
            unsigned e = mxb >> 23;
            sc = __uint_as_float((254u - e) << 23);        // exact 2^(127-e)
            s += (float)((int)e - 127) * 0.6931471805599453f;
        }
    }
    p *= sc;

    float q = p * __expf(ej);
#pragma unroll
    for (int o = 16; o; o >>= 1) q += __shfl_xor_sync(0xffffffffu, q, o);
    float den = s + __logf(q);

    if (j == 0) g_partial[b] = num - den;

    // ---- fused final reduction: last CTA to arrive sums all partials ----
    __threadfence();
    int lastflag = 0;
    if (j == 0) lastflag = (atomicAdd(&g_done, 1) == BB - 1);
    lastflag = __shfl_sync(0xffffffffu, lastflag, 0);
    if (lastflag) {
        __threadfence();
        float v = g_partial[j] + g_partial[j + 32];
#pragma unroll
        for (int o = 16; o; o >>= 1) v += __shfl_xor_sync(0xffffffffu, v, o);
        if (j == 0) {
            out[0] = -v;
            g_done = 0;   // reset for next graph replay
        }
    }
}

// ---------------------------------------------------------------------------
extern "C" void kernel_launch(void* const* d_in, const int* in_sizes, int n_in,
                              void* d_out, int out_size) {
    const float*         X     = (const float*)d_in[0];
    const int*           y     = (const int*)d_in[1];
    const unsigned int*  mask  = (const unsigned int*)d_in[2];
    const float*         W     = (const float*)d_in[3];
    const float*         bias  = (const float*)d_in[4];
    const float*         trans = (const float*)d_in[5];
    const float*         stt   = (const float*)d_in[6];
    const float*         endt  = (const float*)d_in[7];
    float* out = (float*)d_out;

    wtrans_kernel<<<EE / 64, 256>>>(W);
    gemm_kernel<<<MM / RPB, 128>>>(X, bias);
    crf_kernel<<<BB, 32>>>(y, mask, trans, stt, endt, out);
}